// round 13
// baseline (speedup 1.0000x reference)
#include <cuda_runtime.h>
#include <cstdint>

// ---------------- problem constants ----------------
#define SBx   2        // batch
#define CIN   64       // input channels
#define NSP   64000    // 40^3 spatial
#define ECH   128      // encoded channels
#define NHEAD 4
#define CH    32       // channels per head
#define MCTR  8        // 2x2x2 centers
#define OUTC  256
#define UNITS_PER_B 1000   // 64-voxel units per batch
#define BLKS_PER_B  148    // persistent blocks per batch
#define PARTW 1280         // 1024 num + 256 den-group partials
#define CHPAD 160          // padded chunk dim (148 -> 160, 640B rows)

// ---------------- device scratch (static, no allocs) ----------------
__device__ double g_blk[2][SBx][CIN][8];       // octant means (fp64-combined)
__device__ float g_nc[8][MCTR][CH];            // fp32 normalized centers (ref-style norm)
__device__ float g_cc[8][MCTR][CH];            // cond centers (fp32)
__device__ float g_num[8][MCTR][CH];
__device__ float g_den8[SBx][256];             // den partials [b][e*64+m*8+g]
__device__ float g_P[SBx][NHEAD][MCTR][OUTC];  // folded projection
__device__ float g_s[8][NSP];                  // argmax sim value, output order
__device__ unsigned char g_idx[8][NSP];        // argmax index
__device__ float g_partialT[SBx][PARTW][CHPAD]; // partials [b][elem][block-in-b]

__device__ __forceinline__ void cp_async16(uint32_t dst, const void* src) {
    asm volatile("cp.async.cg.shared.global [%0], [%1], 16;" :: "r"(dst), "l"(src));
}

// ---------------- K1: octant means; fp32 row-runs + fp64 register accumulation ----------------
__global__ void k1_blockmeans(const float* __restrict__ x, const float* __restrict__ cond)
{
    int bx = blockIdx.x;          // 0..255 : [tensor(2)][b(2)][cin(64)]
    int t  = bx >> 7;
    int b  = (bx >> 6) & 1;
    int i  = bx & 63;
    const float* src = (t ? cond : x) + (size_t)(b * CIN + i) * NSP;
    int tid = threadIdx.x;

    int q  = tid >> 6;            // (w_hi<<1)|h_hi
    int j  = tid & 63;
    int w0 = (q >> 1) * 20;
    int h0 = (q & 1) * 20;

    double acc_lo = 0.0, acc_hi = 0.0;
    for (int r = j; r < 400; r += 64) {
        int hh = r / 20, ww = r - hh * 20;
        const float4* row = (const float4*)(src + (size_t)(h0 + hh) * 1600 + (w0 + ww) * 40);
        float slo = 0.f, shi = 0.f;
#pragma unroll
        for (int p = 0; p < 5; p++) {
            float4 a = row[p];
            slo += ((a.x + a.y) + (a.z + a.w));
        }
#pragma unroll
        for (int p = 5; p < 10; p++) {
            float4 a = row[p];
            shi += ((a.x + a.y) + (a.z + a.w));
        }
        acc_lo += (double)slo;
        acc_hi += (double)shi;
    }

    __shared__ double dred[256][2];
    dred[tid][0] = acc_lo;
    dred[tid][1] = acc_hi;
    __syncthreads();
    if (tid < 8) {
        int qq = tid >> 1, dbit = tid & 1;
        double s = 0.0;
        for (int jj = 0; jj < 64; jj++) s += dred[qq * 64 + jj][dbit];
        g_blk[t][b][i][tid] = s / 8000.0;
    }
}

// ---------------- K2: centers (fp64 exact GEMM), then ref-style fp32 normalization ----------------
__global__ void k2_centers(const float* __restrict__ xw, const float* __restrict__ xb,
                           const float* __restrict__ cw, const float* __restrict__ cb)
{
    int b9 = blockIdx.x >> 3;     // 0..7  (b*4+e)
    int m  = blockIdx.x & 7;
    int b  = b9 >> 2, e = b9 & 3;
    int c  = threadIdx.x;         // 0..31
    int ec = e * CH + c;

    double cv = 0.0, qv = 0.0;
#pragma unroll 8
    for (int i = 0; i < CIN; i++) {
        cv += (double)xw[ec * CIN + i] * g_blk[0][b][i][m];
        qv += (double)cw[ec * CIN + i] * g_blk[1][b][i][m];
    }
    cv += (double)xb[ec];
    qv += (double)cb[ec];

    float c32 = (float)cv;

    float ssq = 0.f;
    for (int cc = 0; cc < 32; cc++) {
        float v = __shfl_sync(0xffffffffu, c32, cc);
        ssq = __fadd_rn(ssq, __fmul_rn(v, v));
    }
    float nrm = fmaxf(__fsqrt_rn(ssq), 1e-12f);
    g_nc[b9][m][c] = __fdiv_rn(c32, nrm);
    g_cc[b9][m][c] = (float)qv;
}

// ---------------- k_sync: no-op launch so k3_main is launch #4 (ncu skip alignment) ----------------
__global__ void k_sync() {}

// ---------------- K3: persistent fused cond encode + sim + argmax + num/den partials ----------------
#define SW_OFF   0                         // W [128][64]
#define SX_OFF   8192                      // x tile double buffer 2x[64k][64v]
#define SF_OFF   16384                     // feat [128][SF_STR]
#define SF_STR   68                        // multiple of 4: float4 stores need 16B alignment
#define SNC_OFF  (SF_OFF + 128 * SF_STR)   // 25088  centers [4e][32c][8m]
#define SSV_OFF  (SNC_OFF + 1024)          // 26112  (s, idx) pairs [4e][64v][2]
#define SNUM_OFF (SSV_OFF + 512)           // 26624  num partials [2][4][8][32]
#define SB_OFF   (SNUM_OFF + 2048)         // 28672  cond bias [128]
#define SMEM_FLOATS (SB_OFF + 128)         // 28800
#define SMEM_BYTES  (SMEM_FLOATS * 4)      // 115200

extern __shared__ float smem3[];

__device__ __forceinline__ float sigmoid_ref(float x) {
    return __fdiv_rn(1.0f, __fadd_rn(1.0f, expf(-x)));
}

__global__ void __launch_bounds__(256, 2) k3_main(
    const float* __restrict__ cond,
    const float* __restrict__ cw, const float* __restrict__ cbias,
    const float* __restrict__ alpha_p, const float* __restrict__ beta_p)
{
    float* sw  = smem3 + SW_OFF;
    float* sx  = smem3 + SX_OFF;
    float* sf  = smem3 + SF_OFF;
    float* snc = smem3 + SNC_OFF;
    float* ssv = smem3 + SSV_OFF;
    float* snum = smem3 + SNUM_OFF;
    float* sb  = smem3 + SB_OFF;

    int tid = threadIdx.x;
    int bid = blockIdx.x;                 // 0..295
    int b   = (bid >= BLKS_PER_B) ? 1 : 0;
    int lb  = bid - b * BLKS_PER_B;       // 0..147
    int nunits = (UNITS_PER_B - lb + BLKS_PER_B - 1) / BLKS_PER_B;   // 6 or 7
    const float* cbase = cond + (size_t)b * CIN * NSP;

    uint32_t sx_sb = (uint32_t)__cvta_generic_to_shared(sx);

    // prefetch unit 0 into buffer 0 (overlaps with preloads below)
    {
        const float* srcb = cbase + lb * 64;
#pragma unroll
        for (int r = 0; r < 4; r++) {
            int idx = tid + r * 256;       // float4 index 0..1023
            int k = idx >> 4, qd = idx & 15;
            cp_async16(sx_sb + (uint32_t)idx * 16, srcb + (size_t)k * NSP + qd * 4);
        }
        asm volatile("cp.async.commit_group;");
    }

    // preload weights, bias, centers (transposed to [e][c][8m]); zero num partials
#pragma unroll
    for (int r = 0; r < 32; r++) sw[tid + r * 256] = cw[tid + r * 256];
    if (tid < 128) sb[tid] = cbias[tid];
#pragma unroll
    for (int r = 0; r < 4; r++) {
        int idx = tid + r * 256;          // = e*256 + c*8 + m
        int e = idx >> 8, rem = idx & 255;
        int c = rem >> 3, m = rem & 7;
        snc[idx] = g_nc[b * 4 + e][m][c];
    }
#pragma unroll
    for (int r = 0; r < 8; r++) snum[tid + r * 256] = 0.f;

    float alpha = *alpha_p, beta = *beta_p;

    int te = tid >> 4, tv = tid & 15;        // GEMM roles: 8 ec x 4 v per thread
    int ev_v = tid & 63, ev_e = tid >> 6;    // epilogue roles: (v, head)
    int half = tid >> 7, cix = tid & 127;    // accum roles
    int a_e = cix >> 5, a_c = cix & 31;
    int d_e = tid >> 6, d_m = (tid >> 3) & 7, d_g = tid & 7;   // den roles
    float den_acc = 0.f;

    __syncthreads();

    for (int ku = 0; ku < nunits; ku++) {
        int u = lb + ku * BLKS_PER_B;
        // prefetch next unit into other buffer
        if (ku + 1 < nunits) {
            const float* srcb = cbase + (size_t)(u + BLKS_PER_B) * 64;
            uint32_t dstb = sx_sb + (uint32_t)(((ku + 1) & 1) * 4096) * 4;
#pragma unroll
            for (int r = 0; r < 4; r++) {
                int idx = tid + r * 256;
                int k = idx >> 4, qd = idx & 15;
                cp_async16(dstb + (uint32_t)idx * 16, srcb + (size_t)k * NSP + qd * 4);
            }
            asm volatile("cp.async.commit_group;");
            asm volatile("cp.async.wait_group 1;");
        } else {
            asm volatile("cp.async.wait_group 0;");
        }
        __syncthreads();

        const float* sxc = sx + (ku & 1) * 4096;
        int v0 = u * 64;

        // --- register-blocked GEMM: feat[128][64] = W[128][64] * X[64][64] ---
        float acc[8][4];
#pragma unroll
        for (int j = 0; j < 8; j++)
#pragma unroll
            for (int jj = 0; jj < 4; jj++) acc[j][jj] = 0.f;

#pragma unroll 2
        for (int k0 = 0; k0 < 64; k0 += 4) {
            float4 x0 = *(const float4*)&sxc[(k0 + 0) * 64 + tv * 4];
            float4 x1 = *(const float4*)&sxc[(k0 + 1) * 64 + tv * 4];
            float4 x2 = *(const float4*)&sxc[(k0 + 2) * 64 + tv * 4];
            float4 x3 = *(const float4*)&sxc[(k0 + 3) * 64 + tv * 4];
#pragma unroll
            for (int j = 0; j < 8; j++) {
                float4 wr = *(const float4*)&sw[(te * 8 + j) * 64 + k0];
                acc[j][0] = fmaf(wr.w, x3.x, fmaf(wr.z, x2.x, fmaf(wr.y, x1.x, fmaf(wr.x, x0.x, acc[j][0]))));
                acc[j][1] = fmaf(wr.w, x3.y, fmaf(wr.z, x2.y, fmaf(wr.y, x1.y, fmaf(wr.x, x0.y, acc[j][1]))));
                acc[j][2] = fmaf(wr.w, x3.z, fmaf(wr.z, x2.z, fmaf(wr.y, x1.z, fmaf(wr.x, x0.z, acc[j][2]))));
                acc[j][3] = fmaf(wr.w, x3.w, fmaf(wr.z, x2.w, fmaf(wr.y, x1.w, fmaf(wr.x, x0.w, acc[j][3]))));
            }
        }
#pragma unroll
        for (int j = 0; j < 8; j++) {
            int ec = te * 8 + j;
            float bias = sb[ec];
            float4 f4;
            f4.x = __fadd_rn(acc[j][0], bias); f4.y = __fadd_rn(acc[j][1], bias);
            f4.z = __fadd_rn(acc[j][2], bias); f4.w = __fadd_rn(acc[j][3], bias);
            *(float4*)&sf[ec * SF_STR + tv * 4] = f4;
        }
        __syncthreads();

        // --- per (voxel, head): ref-style fp32 norm + sim + argmax ---
        // Streaming-c epilogue: Markstein quotient (bit-exact == __fdiv_rn),
        // centers loaded as float4 pairs [e][c][8m] (broadcast LDS.128).
        {
            int v = ev_v, e = ev_e;
            const float* fbase = &sf[(e * 32) * SF_STR + v];
            float ssq = 0.f;
#pragma unroll
            for (int c = 0; c < 32; c++) {
                float fc = fbase[c * SF_STR];
                ssq = __fadd_rn(ssq, __fmul_rn(fc, fc));
            }
            float nrm = fmaxf(__fsqrt_rn(ssq), 1e-12f);
            float rn_ = __frcp_rn(nrm);     // correctly-rounded reciprocal (Markstein seed)

            float dot[8];
#pragma unroll
            for (int m = 0; m < 8; m++) dot[m] = 0.f;
            const float4* sn4 = (const float4*)&snc[e * 256];
#pragma unroll
            for (int c = 0; c < 32; c++) {
                float fc = fbase[c * SF_STR];
                float q0 = __fmul_rn(fc, rn_);
                float e2 = __fmaf_rn(-nrm, q0, fc);
                float fn = __fmaf_rn(e2, rn_, q0);   // == __fdiv_rn(fc, nrm), bit-exact
                float4 A = sn4[c * 2];
                float4 B = sn4[c * 2 + 1];
                dot[0] = fmaf(A.x, fn, dot[0]);
                dot[1] = fmaf(A.y, fn, dot[1]);
                dot[2] = fmaf(A.z, fn, dot[2]);
                dot[3] = fmaf(A.w, fn, dot[3]);
                dot[4] = fmaf(B.x, fn, dot[4]);
                dot[5] = fmaf(B.y, fn, dot[5]);
                dot[6] = fmaf(B.z, fn, dot[6]);
                dot[7] = fmaf(B.w, fn, dot[7]);
            }

            float t[8];
#pragma unroll
            for (int m = 0; m < 8; m++)
                t[m] = __fadd_rn(beta, __fmul_rn(alpha, dot[m]));

            float best = t[0], second = -3.4e38f; int bm = 0;
#pragma unroll
            for (int m = 1; m < 8; m++) {
                if (t[m] > best) { second = best; best = t[m]; bm = m; }
                else if (t[m] > second) second = t[m];
            }
            float sv;
            if (best - second > 4e-6f) {
                sv = sigmoid_ref(best);
            } else {
                float bs = -1.f; bm = 0;
#pragma unroll
                for (int m = 0; m < 8; m++) {
                    float sm = sigmoid_ref(t[m]);
                    if (sm > bs) { bs = sm; bm = m; }
                }
                sv = bs;
            }
            float2 pr;
            pr.x = sv;
            pr.y = __int_as_float(bm);
            *(float2*)&ssv[(e * 64 + v) * 2] = pr;
            int vlin = v0 + v;
            int h = vlin / 1600;
            int r = vlin - h * 1600;
            int w = r / 40;
            int d = r - w * 40;
            int nout = w * 1600 + h * 40 + d;
            g_s[b * 4 + e][nout] = sv;
            g_idx[b * 4 + e][nout] = (unsigned char)bm;
        }
        __syncthreads();

        // --- num accumulation, bank-conflict-free via a_c skew; (s,idx) as LDS.64 pairs ---
        {
            const float* frow = &sf[(a_e * 32 + a_c) * SF_STR + half * 32];
            const float2* prow = (const float2*)&ssv[(a_e * 64 + half * 32) * 2];
            float na[8];
#pragma unroll
            for (int m = 0; m < 8; m++) na[m] = 0.f;
#pragma unroll 8
            for (int vv = 0; vv < 32; vv++) {
                int ve = (vv + a_c) & 31;     // skew: conflict-free f reads
                float2 pr = prow[ve];
                float p = pr.x * frow[ve];
                int am = __float_as_int(pr.y);
#pragma unroll
                for (int m = 0; m < 8; m++) na[m] += (m == am) ? p : 0.f;
            }
#pragma unroll
            for (int m = 0; m < 8; m++) snum[((half * 4 + a_e) * 8 + m) * 32 + a_c] += na[m];
        }
        // --- den partials: all 256 threads, (e, m, voxel-group-of-8) roles ---
        {
            const float2* pden = (const float2*)&ssv[(d_e * 64 + d_g * 8) * 2];
            float da = 0.f;
#pragma unroll
            for (int i = 0; i < 8; i++) {
                float2 pr = pden[i];
                da += (__float_as_int(pr.y) == d_m) ? pr.x : 0.f;
            }
            den_acc += da;
        }
        __syncthreads();
    }

    // deterministic partials (no atomics), transposed layout for coalesced reduce
#pragma unroll
    for (int r = 0; r < 4; r++) {
        int i = tid + r * 256;
        g_partialT[b][i][lb] = snum[i] + snum[1024 + i];
    }
    g_partialT[b][1024 + tid][lb] = den_acc;
}

// ---------------- Kred: warp-per-element coalesced deterministic reduction ----------------
// 2560 elements, one warp each -> 320 blocks of 256
__global__ void k_red()
{
    int el   = blockIdx.x * 8 + (threadIdx.x >> 5);   // 0..2559
    int lane = threadIdx.x & 31;
    int b  = el / PARTW;
    int i  = el - b * PARTW;
    float sum = 0.f;
#pragma unroll
    for (int blk = lane; blk < BLKS_PER_B; blk += 32)
        sum += g_partialT[b][i][blk];
    sum += __shfl_xor_sync(0xffffffffu, sum, 16);
    sum += __shfl_xor_sync(0xffffffffu, sum, 8);
    sum += __shfl_xor_sync(0xffffffffu, sum, 4);
    sum += __shfl_xor_sync(0xffffffffu, sum, 2);
    sum += __shfl_xor_sync(0xffffffffu, sum, 1);
    if (lane == 0) {
        if (i < 1024) {
            (&g_num[0][0][0])[b * 1024 + i] = sum;
        } else {
            g_den8[b][i - 1024] = sum;     // [e*64 + m*8 + g]
        }
    }
}

// ---------------- K4: fold w into projection -> P ----------------
__global__ void k4_P(const float* __restrict__ pw)
{
    int b9 = blockIdx.x >> 3;
    int m  = blockIdx.x & 7;
    int b  = b9 >> 2, e = b9 & 3;
    __shared__ float wsh[32];
    int tid = threadIdx.x;   // 0..255 = o
    if (tid < 32) {
        float den = 0.f;
#pragma unroll
        for (int g = 0; g < 8; g++) den += g_den8[b][e * 64 + m * 8 + g];
        wsh[tid] = __fdiv_rn(__fadd_rn(g_num[b9][m][tid], g_cc[b9][m][tid]),
                             __fadd_rn(den, 1.0f));
    }
    __syncthreads();
    float p = 0.f;
#pragma unroll 8
    for (int c = 0; c < 32; c++) p = fmaf(pw[tid * ECH + e * CH + c], wsh[c], p);
    g_P[b][e][m][tid] = p;
}

// ---------------- K5: output = proj_b + sum_e s_e * P[b][e][idx_e][:] ----------------
#define PPAD 257
__global__ void __launch_bounds__(128) k5_out(const float* __restrict__ pb, float* __restrict__ out)
{
    __shared__ float Ps[32 * PPAD];
    __shared__ float pbs[256];
    int tid = threadIdx.x;
    int bx  = blockIdx.x;
    int b   = bx / 125;
    int chunk = bx - b * 125;

    const float* Pg = &g_P[b][0][0][0];
#pragma unroll
    for (int r = 0; r < 64; r++) {
        int idx = tid + r * 128;            // 0..8191
        int em = idx >> 8, o = idx & 255;
        Ps[em * PPAD + o] = Pg[idx];
    }
#pragma unroll
    for (int r = 0; r < 2; r++) pbs[tid + r * 128] = pb[tid + r * 128];

    int n0 = chunk * 512 + tid * 4;
    float4 sv[4];
    int off[4][4];
#pragma unroll
    for (int e = 0; e < 4; e++) {
        sv[e] = *(const float4*)&g_s[b * 4 + e][n0];
        uchar4 id = *(const uchar4*)&g_idx[b * 4 + e][n0];
        off[e][0] = (e * 8 + id.x) * PPAD;
        off[e][1] = (e * 8 + id.y) * PPAD;
        off[e][2] = (e * 8 + id.z) * PPAD;
        off[e][3] = (e * 8 + id.w) * PPAD;
    }
    __syncthreads();

    float* ob = out + (size_t)b * OUTC * NSP + n0;
#pragma unroll 4
    for (int o = 0; o < 256; o++) {
        float pbv = pbs[o];
        float4 a = make_float4(pbv, pbv, pbv, pbv);
#pragma unroll
        for (int e = 0; e < 4; e++) {
            a.x = fmaf(sv[e].x, Ps[off[e][0] + o], a.x);
            a.y = fmaf(sv[e].y, Ps[off[e][1] + o], a.y);
            a.z = fmaf(sv[e].z, Ps[off[e][2] + o], a.z);
            a.w = fmaf(sv[e].w, Ps[off[e][3] + o], a.w);
        }
        *(float4*)&ob[(size_t)o * NSP] = a;
    }
}

// ---------------- launch ----------------
extern "C" void kernel_launch(void* const* d_in, const int* in_sizes, int n_in,
                              void* d_out, int out_size)
{
    const float* x     = (const float*)d_in[0];
    const float* cond  = (const float*)d_in[1];
    const float* xw    = (const float*)d_in[2];
    const float* xb    = (const float*)d_in[3];
    const float* cw    = (const float*)d_in[4];
    const float* cb    = (const float*)d_in[5];
    const float* alpha = (const float*)d_in[6];
    const float* beta  = (const float*)d_in[7];
    const float* pw    = (const float*)d_in[8];
    const float* pb    = (const float*)d_in[9];
    float* out = (float*)d_out;
    (void)in_sizes; (void)n_in; (void)out_size;

    cudaFuncSetAttribute(k3_main, cudaFuncAttributeMaxDynamicSharedMemorySize, SMEM_BYTES);

    k1_blockmeans<<<256, 256>>>(x, cond);
    k2_centers<<<64, 32>>>(xw, xb, cw, cb);
    k_sync<<<1, 32>>>();    // alignment: make k3_main launch #4 so ncu profiles it
    k3_main<<<2 * BLKS_PER_B, 256, SMEM_BYTES>>>(cond, cw, cb, alpha, beta);
    k_red<<<320, 256>>>();
    k4_P<<<64, 256>>>(pw);
    k5_out<<<2 * 125, 128>>>(pb, out);
}

// round 14
// speedup vs baseline: 1.0891x; 1.0891x over previous
#include <cuda_runtime.h>
#include <cstdint>

// ---------------- problem constants ----------------
#define SBx   2        // batch
#define CIN   64       // input channels
#define NSP   64000    // 40^3 spatial
#define ECH   128      // encoded channels
#define NHEAD 4
#define CH    32       // channels per head
#define MCTR  8        // 2x2x2 centers
#define OUTC  256
#define UNITS_PER_B 1000   // 64-voxel units per batch
#define BLKS_PER_B  148    // persistent blocks per batch
#define PARTW 1280         // 1024 num + 256 den-group partials
#define CHPAD 160          // padded chunk dim (148 -> 160, 640B rows)

// ---------------- device scratch (static, no allocs) ----------------
__device__ double g_blk[2][SBx][CIN][8];       // octant means (fp64-combined)
__device__ float g_nc[8][MCTR][CH];            // fp32 normalized centers (ref-style norm)
__device__ float g_cc[8][MCTR][CH];            // cond centers (fp32)
__device__ float g_num[8][MCTR][CH];
__device__ float g_den8[SBx][256];             // den partials [b][e*64+m*8+g]
__device__ float g_P[SBx][NHEAD][MCTR][OUTC];  // folded projection
__device__ float g_s[8][NSP];                  // argmax sim value, output order
__device__ unsigned char g_idx[8][NSP];        // argmax index
__device__ float g_partialT[SBx][PARTW][CHPAD]; // partials [b][elem][block-in-b]

__device__ __forceinline__ void cp_async16(uint32_t dst, const void* src) {
    asm volatile("cp.async.cg.shared.global [%0], [%1], 16;" :: "r"(dst), "l"(src));
}

// ---------------- K1: octant means; fp32 row-runs + fp64 register accumulation ----------------
__global__ void k1_blockmeans(const float* __restrict__ x, const float* __restrict__ cond)
{
    int bx = blockIdx.x;          // 0..255 : [tensor(2)][b(2)][cin(64)]
    int t  = bx >> 7;
    int b  = (bx >> 6) & 1;
    int i  = bx & 63;
    const float* src = (t ? cond : x) + (size_t)(b * CIN + i) * NSP;
    int tid = threadIdx.x;

    int q  = tid >> 6;            // (w_hi<<1)|h_hi
    int j  = tid & 63;
    int w0 = (q >> 1) * 20;
    int h0 = (q & 1) * 20;

    double acc_lo = 0.0, acc_hi = 0.0;
    for (int r = j; r < 400; r += 64) {
        int hh = r / 20, ww = r - hh * 20;
        const float4* row = (const float4*)(src + (size_t)(h0 + hh) * 1600 + (w0 + ww) * 40);
        float slo = 0.f, shi = 0.f;
#pragma unroll
        for (int p = 0; p < 5; p++) {
            float4 a = row[p];
            slo += ((a.x + a.y) + (a.z + a.w));
        }
#pragma unroll
        for (int p = 5; p < 10; p++) {
            float4 a = row[p];
            shi += ((a.x + a.y) + (a.z + a.w));
        }
        acc_lo += (double)slo;
        acc_hi += (double)shi;
    }

    __shared__ double dred[256][2];
    dred[tid][0] = acc_lo;
    dred[tid][1] = acc_hi;
    __syncthreads();
    if (tid < 8) {
        int qq = tid >> 1, dbit = tid & 1;
        double s = 0.0;
        for (int jj = 0; jj < 64; jj++) s += dred[qq * 64 + jj][dbit];
        g_blk[t][b][i][tid] = s / 8000.0;
    }
}

// ---------------- K2: centers (fp64 exact GEMM), then ref-style fp32 normalization ----------------
__global__ void k2_centers(const float* __restrict__ xw, const float* __restrict__ xb,
                           const float* __restrict__ cw, const float* __restrict__ cb)
{
    int b9 = blockIdx.x >> 3;     // 0..7  (b*4+e)
    int m  = blockIdx.x & 7;
    int b  = b9 >> 2, e = b9 & 3;
    int c  = threadIdx.x;         // 0..31
    int ec = e * CH + c;

    double cv = 0.0, qv = 0.0;
#pragma unroll 8
    for (int i = 0; i < CIN; i++) {
        cv += (double)xw[ec * CIN + i] * g_blk[0][b][i][m];
        qv += (double)cw[ec * CIN + i] * g_blk[1][b][i][m];
    }
    cv += (double)xb[ec];
    qv += (double)cb[ec];

    float c32 = (float)cv;

    float ssq = 0.f;
    for (int cc = 0; cc < 32; cc++) {
        float v = __shfl_sync(0xffffffffu, c32, cc);
        ssq = __fadd_rn(ssq, __fmul_rn(v, v));
    }
    float nrm = fmaxf(__fsqrt_rn(ssq), 1e-12f);
    g_nc[b9][m][c] = __fdiv_rn(c32, nrm);
    g_cc[b9][m][c] = (float)qv;
}

// ---------------- K3: persistent fused cond encode + sim + argmax + num/den partials ----------------
#define SW_OFF   0                         // W [128][64]
#define SX_OFF   8192                      // x tile double buffer 2x[64k][64v]
#define SF_OFF   16384                     // feat [128][SF_STR]
#define SF_STR   68                        // multiple of 4: float4 stores need 16B alignment
#define SNC_OFF  (SF_OFF + 128 * SF_STR)   // 25088  centers [4e][8m][32c]
#define SS_OFF   (SNC_OFF + 1024)          // 26112  s per (e,v)
#define SIDX_OFF (SS_OFF + 256)            // 26368  idx per (e,v)
#define SNUM_OFF (SIDX_OFF + 256)          // 26624  num partials [2][4][8][32]
#define SB_OFF   (SNUM_OFF + 2048)         // 28672  cond bias [128]
#define SMEM_FLOATS (SB_OFF + 128)         // 28800
#define SMEM_BYTES  (SMEM_FLOATS * 4)      // 115200

extern __shared__ float smem3[];

__device__ __forceinline__ float sigmoid_ref(float x) {
    return __fdiv_rn(1.0f, __fadd_rn(1.0f, expf(-x)));
}

__global__ void __launch_bounds__(256, 2) k3_main(
    const float* __restrict__ cond,
    const float* __restrict__ cw, const float* __restrict__ cbias,
    const float* __restrict__ alpha_p, const float* __restrict__ beta_p)
{
    float* sw  = smem3 + SW_OFF;
    float* sx  = smem3 + SX_OFF;
    float* sf  = smem3 + SF_OFF;
    float* snc = smem3 + SNC_OFF;
    float* ss  = smem3 + SS_OFF;
    int*   sidx = (int*)(smem3 + SIDX_OFF);
    float* snum = smem3 + SNUM_OFF;
    float* sb  = smem3 + SB_OFF;

    int tid = threadIdx.x;
    int bid = blockIdx.x;                 // 0..295
    int b   = (bid >= BLKS_PER_B) ? 1 : 0;
    int lb  = bid - b * BLKS_PER_B;       // 0..147
    int nunits = (UNITS_PER_B - lb + BLKS_PER_B - 1) / BLKS_PER_B;   // 6 or 7
    const float* cbase = cond + (size_t)b * CIN * NSP;

    uint32_t sx_sb = (uint32_t)__cvta_generic_to_shared(sx);

    // prefetch unit 0 into buffer 0 (overlaps with preloads below)
    {
        const float* srcb = cbase + lb * 64;
#pragma unroll
        for (int r = 0; r < 4; r++) {
            int idx = tid + r * 256;       // float4 index 0..1023
            int k = idx >> 4, qd = idx & 15;
            cp_async16(sx_sb + (uint32_t)idx * 16, srcb + (size_t)k * NSP + qd * 4);
        }
        asm volatile("cp.async.commit_group;");
    }

    // preload weights, bias, centers; zero num partials
#pragma unroll
    for (int r = 0; r < 32; r++) sw[tid + r * 256] = cw[tid + r * 256];
    if (tid < 128) sb[tid] = cbias[tid];
#pragma unroll
    for (int r = 0; r < 4; r++) snc[tid + r * 256] = (&g_nc[0][0][0])[b * 1024 + tid + r * 256];
#pragma unroll
    for (int r = 0; r < 8; r++) snum[tid + r * 256] = 0.f;

    float alpha = *alpha_p, beta = *beta_p;

    int te = tid >> 4, tv = tid & 15;        // GEMM roles: 8 ec x 4 v per thread
    int ev_v = tid & 63, ev_e = tid >> 6;    // epilogue roles: (v, head)
    int half = tid >> 7, cix = tid & 127;    // accum roles
    int a_e = cix >> 5, a_c = cix & 31;
    int d_e = tid >> 6, d_m = (tid >> 3) & 7, d_g = tid & 7;   // den roles
    float den_acc = 0.f;

    __syncthreads();

    for (int ku = 0; ku < nunits; ku++) {
        int u = lb + ku * BLKS_PER_B;
        // prefetch next unit into other buffer
        if (ku + 1 < nunits) {
            const float* srcb = cbase + (size_t)(u + BLKS_PER_B) * 64;
            uint32_t dstb = sx_sb + (uint32_t)(((ku + 1) & 1) * 4096) * 4;
#pragma unroll
            for (int r = 0; r < 4; r++) {
                int idx = tid + r * 256;
                int k = idx >> 4, qd = idx & 15;
                cp_async16(dstb + (uint32_t)idx * 16, srcb + (size_t)k * NSP + qd * 4);
            }
            asm volatile("cp.async.commit_group;");
            asm volatile("cp.async.wait_group 1;");
        } else {
            asm volatile("cp.async.wait_group 0;");
        }
        __syncthreads();

        const float* sxc = sx + (ku & 1) * 4096;
        int v0 = u * 64;

        // --- register-blocked GEMM: feat[128][64] = W[128][64] * X[64][64] ---
        float acc[8][4];
#pragma unroll
        for (int j = 0; j < 8; j++)
#pragma unroll
            for (int jj = 0; jj < 4; jj++) acc[j][jj] = 0.f;

#pragma unroll 2
        for (int k0 = 0; k0 < 64; k0 += 4) {
            float4 x0 = *(const float4*)&sxc[(k0 + 0) * 64 + tv * 4];
            float4 x1 = *(const float4*)&sxc[(k0 + 1) * 64 + tv * 4];
            float4 x2 = *(const float4*)&sxc[(k0 + 2) * 64 + tv * 4];
            float4 x3 = *(const float4*)&sxc[(k0 + 3) * 64 + tv * 4];
#pragma unroll
            for (int j = 0; j < 8; j++) {
                float4 wr = *(const float4*)&sw[(te * 8 + j) * 64 + k0];
                acc[j][0] = fmaf(wr.w, x3.x, fmaf(wr.z, x2.x, fmaf(wr.y, x1.x, fmaf(wr.x, x0.x, acc[j][0]))));
                acc[j][1] = fmaf(wr.w, x3.y, fmaf(wr.z, x2.y, fmaf(wr.y, x1.y, fmaf(wr.x, x0.y, acc[j][1]))));
                acc[j][2] = fmaf(wr.w, x3.z, fmaf(wr.z, x2.z, fmaf(wr.y, x1.z, fmaf(wr.x, x0.z, acc[j][2]))));
                acc[j][3] = fmaf(wr.w, x3.w, fmaf(wr.z, x2.w, fmaf(wr.y, x1.w, fmaf(wr.x, x0.w, acc[j][3]))));
            }
        }
#pragma unroll
        for (int j = 0; j < 8; j++) {
            int ec = te * 8 + j;
            float bias = sb[ec];
            float4 f4;
            f4.x = __fadd_rn(acc[j][0], bias); f4.y = __fadd_rn(acc[j][1], bias);
            f4.z = __fadd_rn(acc[j][2], bias); f4.w = __fadd_rn(acc[j][3], bias);
            *(float4*)&sf[ec * SF_STR + tv * 4] = f4;
        }
        __syncthreads();

        // --- per (voxel, head): ref-style fp32 norm + sim + argmax ---
        // Streaming-c epilogue: Markstein quotient (bit-exact == __fdiv_rn)
        {
            int v = ev_v, e = ev_e;
            const float* fbase = &sf[(e * 32) * SF_STR + v];
            float ssq = 0.f;
#pragma unroll
            for (int c = 0; c < 32; c++) {
                float fc = fbase[c * SF_STR];
                ssq = __fadd_rn(ssq, __fmul_rn(fc, fc));
            }
            float nrm = fmaxf(__fsqrt_rn(ssq), 1e-12f);
            float rn_ = __frcp_rn(nrm);     // correctly-rounded reciprocal (Markstein seed)

            float dot[8];
#pragma unroll
            for (int m = 0; m < 8; m++) dot[m] = 0.f;
            const float* sncb = &snc[e * 8 * 32];
#pragma unroll
            for (int c = 0; c < 32; c++) {
                float fc = fbase[c * SF_STR];
                float q0 = __fmul_rn(fc, rn_);
                float e2 = __fmaf_rn(-nrm, q0, fc);
                float fn = __fmaf_rn(e2, rn_, q0);   // == __fdiv_rn(fc, nrm), bit-exact
#pragma unroll
                for (int m = 0; m < 8; m++)
                    dot[m] = fmaf(sncb[m * 32 + c], fn, dot[m]);
            }

            float t[8];
#pragma unroll
            for (int m = 0; m < 8; m++)
                t[m] = __fadd_rn(beta, __fmul_rn(alpha, dot[m]));

            float best = t[0], second = -3.4e38f; int bm = 0;
#pragma unroll
            for (int m = 1; m < 8; m++) {
                if (t[m] > best) { second = best; best = t[m]; bm = m; }
                else if (t[m] > second) second = t[m];
            }
            float sv;
            if (best - second > 4e-6f) {
                sv = sigmoid_ref(best);
            } else {
                float bs = -1.f; bm = 0;
#pragma unroll
                for (int m = 0; m < 8; m++) {
                    float sm = sigmoid_ref(t[m]);
                    if (sm > bs) { bs = sm; bm = m; }
                }
                sv = bs;
            }
            ss[e * 64 + v] = sv;
            sidx[e * 64 + v] = bm;
            int vlin = v0 + v;
            int h = vlin / 1600;
            int r = vlin - h * 1600;
            int w = r / 40;
            int d = r - w * 40;
            int nout = w * 1600 + h * 40 + d;
            g_s[b * 4 + e][nout] = sv;
            g_idx[b * 4 + e][nout] = (unsigned char)bm;
        }
        __syncthreads();

        // --- num accumulation: direct-indexed smem RMW, exclusive conflict-free slots ---
        // slot bank = a_c (stride-32 per m) -> conflict-free; per-thread serial ->
        // deterministic. Replaces 8-way predicated select (issue-slot heavy).
        {
            const float* frow = &sf[(a_e * 32 + a_c) * SF_STR + half * 32];
            const float* srow = &ss[a_e * 64 + half * 32];
            const int*   mrow = &sidx[a_e * 64 + half * 32];
            float* nbase = &snum[((half * 4 + a_e) * 8) * 32 + a_c];
#pragma unroll 8
            for (int vv = 0; vv < 32; vv++) {
                int ve = (vv + a_c) & 31;     // skew: conflict-free f reads
                float p = srow[ve] * frow[ve];
                int am = mrow[ve];
                nbase[am * 32] += p;
            }
        }
        // --- den partials: all 256 threads, (e, m, voxel-group-of-8) roles ---
        {
            const float* sden = &ss[d_e * 64 + d_g * 8];
            const int*   midx = &sidx[d_e * 64 + d_g * 8];
            float da = 0.f;
#pragma unroll
            for (int i = 0; i < 8; i++)
                da += (midx[i] == d_m) ? sden[i] : 0.f;
            den_acc += da;
        }
        __syncthreads();
    }

    // deterministic partials (no atomics), transposed layout for coalesced reduce
#pragma unroll
    for (int r = 0; r < 4; r++) {
        int i = tid + r * 256;
        g_partialT[b][i][lb] = snum[i] + snum[1024 + i];
    }
    g_partialT[b][1024 + tid][lb] = den_acc;
}

// ---------------- Kred: warp-per-element coalesced deterministic reduction ----------------
// 2560 elements, one warp each -> 320 blocks of 256
__global__ void k_red()
{
    int el   = blockIdx.x * 8 + (threadIdx.x >> 5);   // 0..2559
    int lane = threadIdx.x & 31;
    int b  = el / PARTW;
    int i  = el - b * PARTW;
    float sum = 0.f;
#pragma unroll
    for (int blk = lane; blk < BLKS_PER_B; blk += 32)
        sum += g_partialT[b][i][blk];
    sum += __shfl_xor_sync(0xffffffffu, sum, 16);
    sum += __shfl_xor_sync(0xffffffffu, sum, 8);
    sum += __shfl_xor_sync(0xffffffffu, sum, 4);
    sum += __shfl_xor_sync(0xffffffffu, sum, 2);
    sum += __shfl_xor_sync(0xffffffffu, sum, 1);
    if (lane == 0) {
        if (i < 1024) {
            (&g_num[0][0][0])[b * 1024 + i] = sum;
        } else {
            g_den8[b][i - 1024] = sum;     // [e*64 + m*8 + g]
        }
    }
}

// ---------------- K4: fold w into projection -> P ----------------
__global__ void k4_P(const float* __restrict__ pw)
{
    int b9 = blockIdx.x >> 3;
    int m  = blockIdx.x & 7;
    int b  = b9 >> 2, e = b9 & 3;
    __shared__ float wsh[32];
    int tid = threadIdx.x;   // 0..255 = o
    if (tid < 32) {
        float den = 0.f;
#pragma unroll
        for (int g = 0; g < 8; g++) den += g_den8[b][e * 64 + m * 8 + g];
        wsh[tid] = __fdiv_rn(__fadd_rn(g_num[b9][m][tid], g_cc[b9][m][tid]),
                             __fadd_rn(den, 1.0f));
    }
    __syncthreads();
    float p = 0.f;
#pragma unroll 8
    for (int c = 0; c < 32; c++) p = fmaf(pw[tid * ECH + e * CH + c], wsh[c], p);
    g_P[b][e][m][tid] = p;
}

// ---------------- K5: output = proj_b + sum_e s_e * P[b][e][idx_e][:] ----------------
#define PPAD 257
__global__ void __launch_bounds__(128) k5_out(const float* __restrict__ pb, float* __restrict__ out)
{
    __shared__ float Ps[32 * PPAD];
    __shared__ float pbs[256];
    int tid = threadIdx.x;
    int bx  = blockIdx.x;
    int b   = bx / 125;
    int chunk = bx - b * 125;

    const float* Pg = &g_P[b][0][0][0];
#pragma unroll
    for (int r = 0; r < 64; r++) {
        int idx = tid + r * 128;            // 0..8191
        int em = idx >> 8, o = idx & 255;
        Ps[em * PPAD + o] = Pg[idx];
    }
#pragma unroll
    for (int r = 0; r < 2; r++) pbs[tid + r * 128] = pb[tid + r * 128];

    int n0 = chunk * 512 + tid * 4;
    float4 sv[4];
    int off[4][4];
#pragma unroll
    for (int e = 0; e < 4; e++) {
        sv[e] = *(const float4*)&g_s[b * 4 + e][n0];
        uchar4 id = *(const uchar4*)&g_idx[b * 4 + e][n0];
        off[e][0] = (e * 8 + id.x) * PPAD;
        off[e][1] = (e * 8 + id.y) * PPAD;
        off[e][2] = (e * 8 + id.z) * PPAD;
        off[e][3] = (e * 8 + id.w) * PPAD;
    }
    __syncthreads();

    float* ob = out + (size_t)b * OUTC * NSP + n0;
#pragma unroll 4
    for (int o = 0; o < 256; o++) {
        float pbv = pbs[o];
        float4 a = make_float4(pbv, pbv, pbv, pbv);
#pragma unroll
        for (int e = 0; e < 4; e++) {
            a.x = fmaf(sv[e].x, Ps[off[e][0] + o], a.x);
            a.y = fmaf(sv[e].y, Ps[off[e][1] + o], a.y);
            a.z = fmaf(sv[e].z, Ps[off[e][2] + o], a.z);
            a.w = fmaf(sv[e].w, Ps[off[e][3] + o], a.w);
        }
        *(float4*)&ob[(size_t)o * NSP] = a;
    }
}

// ---------------- launch ----------------
extern "C" void kernel_launch(void* const* d_in, const int* in_sizes, int n_in,
                              void* d_out, int out_size)
{
    const float* x     = (const float*)d_in[0];
    const float* cond  = (const float*)d_in[1];
    const float* xw    = (const float*)d_in[2];
    const float* xb    = (const float*)d_in[3];
    const float* cw    = (const float*)d_in[4];
    const float* cb    = (const float*)d_in[5];
    const float* alpha = (const float*)d_in[6];
    const float* beta  = (const float*)d_in[7];
    const float* pw    = (const float*)d_in[8];
    const float* pb    = (const float*)d_in[9];
    float* out = (float*)d_out;
    (void)in_sizes; (void)n_in; (void)out_size;

    cudaFuncSetAttribute(k3_main, cudaFuncAttributeMaxDynamicSharedMemorySize, SMEM_BYTES);

    k1_blockmeans<<<256, 256>>>(x, cond);
    k2_centers<<<64, 32>>>(xw, xb, cw, cb);
    k3_main<<<2 * BLKS_PER_B, 256, SMEM_BYTES>>>(cond, cw, cb, alpha, beta);
    k_red<<<320, 256>>>();
    k4_P<<<64, 256>>>(pw);
    k5_out<<<2 * 125, 128>>>(pb, out);
}

// round 15
// speedup vs baseline: 1.0937x; 1.0043x over previous
#include <cuda_runtime.h>
#include <cstdint>

// ---------------- problem constants ----------------
#define SBx   2        // batch
#define CIN   64       // input channels
#define NSP   64000    // 40^3 spatial
#define ECH   128      // encoded channels
#define NHEAD 4
#define CH    32       // channels per head
#define MCTR  8        // 2x2x2 centers
#define OUTC  256
#define UNITS_PER_B 1000   // 64-voxel units per batch
#define BLKS_PER_B  148    // persistent blocks per batch
#define PARTW 1280         // 1024 num + 256 den-group partials
#define CHPAD 160          // padded chunk dim (148 -> 160, 640B rows)

// ---------------- device scratch (static, no allocs) ----------------
__device__ double g_blk[2][SBx][CIN][8];       // octant means (fp64-combined)
__device__ float g_nc[8][MCTR][CH];            // fp32 normalized centers (ref-style norm)
__device__ float g_cc[8][MCTR][CH];            // cond centers (fp32)
__device__ float g_num[8][MCTR][CH];
__device__ float g_den8[SBx][256];             // den partials [b][e*64+m*8+g]
__device__ float g_P[SBx][NHEAD][MCTR][OUTC];  // folded projection
__device__ float g_s[8][NSP];                  // argmax sim value, output order
__device__ unsigned char g_idx[8][NSP];        // argmax index
__device__ float g_partialT[SBx][PARTW][CHPAD]; // partials [b][elem][block-in-b]

__device__ __forceinline__ void cp_async16(uint32_t dst, const void* src) {
    asm volatile("cp.async.cg.shared.global [%0], [%1], 16;" :: "r"(dst), "l"(src));
}

// ---------------- K1: octant means; fp32 row-runs + fp64 register accumulation ----------------
__global__ void k1_blockmeans(const float* __restrict__ x, const float* __restrict__ cond)
{
    int bx = blockIdx.x;          // 0..255 : [tensor(2)][b(2)][cin(64)]
    int t  = bx >> 7;
    int b  = (bx >> 6) & 1;
    int i  = bx & 63;
    const float* src = (t ? cond : x) + (size_t)(b * CIN + i) * NSP;
    int tid = threadIdx.x;

    int q  = tid >> 6;            // (w_hi<<1)|h_hi
    int j  = tid & 63;
    int w0 = (q >> 1) * 20;
    int h0 = (q & 1) * 20;

    double acc_lo = 0.0, acc_hi = 0.0;
    for (int r = j; r < 400; r += 64) {
        int hh = r / 20, ww = r - hh * 20;
        const float4* row = (const float4*)(src + (size_t)(h0 + hh) * 1600 + (w0 + ww) * 40);
        float slo = 0.f, shi = 0.f;
#pragma unroll
        for (int p = 0; p < 5; p++) {
            float4 a = row[p];
            slo += ((a.x + a.y) + (a.z + a.w));
        }
#pragma unroll
        for (int p = 5; p < 10; p++) {
            float4 a = row[p];
            shi += ((a.x + a.y) + (a.z + a.w));
        }
        acc_lo += (double)slo;
        acc_hi += (double)shi;
    }

    __shared__ double dred[256][2];
    dred[tid][0] = acc_lo;
    dred[tid][1] = acc_hi;
    __syncthreads();
    if (tid < 8) {
        int qq = tid >> 1, dbit = tid & 1;
        double s = 0.0;
        for (int jj = 0; jj < 64; jj++) s += dred[qq * 64 + jj][dbit];
        g_blk[t][b][i][tid] = s / 8000.0;
    }
}

// ---------------- K2: centers (fp64 exact GEMM), then ref-style fp32 normalization ----------------
__global__ void k2_centers(const float* __restrict__ xw, const float* __restrict__ xb,
                           const float* __restrict__ cw, const float* __restrict__ cb)
{
    int b9 = blockIdx.x >> 3;     // 0..7  (b*4+e)
    int m  = blockIdx.x & 7;
    int b  = b9 >> 2, e = b9 & 3;
    int c  = threadIdx.x;         // 0..31
    int ec = e * CH + c;

    double cv = 0.0, qv = 0.0;
#pragma unroll 8
    for (int i = 0; i < CIN; i++) {
        cv += (double)xw[ec * CIN + i] * g_blk[0][b][i][m];
        qv += (double)cw[ec * CIN + i] * g_blk[1][b][i][m];
    }
    cv += (double)xb[ec];
    qv += (double)cb[ec];

    float c32 = (float)cv;

    float ssq = 0.f;
    for (int cc = 0; cc < 32; cc++) {
        float v = __shfl_sync(0xffffffffu, c32, cc);
        ssq = __fadd_rn(ssq, __fmul_rn(v, v));
    }
    float nrm = fmaxf(__fsqrt_rn(ssq), 1e-12f);
    g_nc[b9][m][c] = __fdiv_rn(c32, nrm);
    g_cc[b9][m][c] = (float)qv;
}

// ---------------- K3: persistent fused cond encode + sim + argmax + num/den partials ----------------
#define SW_OFF   0                         // W [128][64]
#define SX_OFF   8192                      // x tile double buffer 2x[64k][64v]
#define SF_OFF   16384                     // feat [128][SF_STR]
#define SF_STR   68                        // multiple of 4: float4 stores need 16B alignment
#define SNC_OFF  (SF_OFF + 128 * SF_STR)   // 25088  centers [4e][8m][32c]
#define SS_OFF   (SNC_OFF + 1024)          // 26112  s per (e,v)
#define SIDX_OFF (SS_OFF + 256)            // 26368  idx per (e,v)
#define SNUM_OFF (SIDX_OFF + 256)          // 26624  num partials [2][4][8][32]
#define SB_OFF   (SNUM_OFF + 2048)         // 28672  cond bias [128]
#define SMEM_FLOATS (SB_OFF + 128)         // 28800
#define SMEM_BYTES  (SMEM_FLOATS * 4)      // 115200

extern __shared__ float smem3[];

__device__ __forceinline__ float sigmoid_ref(float x) {
    return __fdiv_rn(1.0f, __fadd_rn(1.0f, expf(-x)));
}

__global__ void __launch_bounds__(256, 2) k3_main(
    const float* __restrict__ cond,
    const float* __restrict__ cw, const float* __restrict__ cbias,
    const float* __restrict__ alpha_p, const float* __restrict__ beta_p)
{
    float* sw  = smem3 + SW_OFF;
    float* sx  = smem3 + SX_OFF;
    float* sf  = smem3 + SF_OFF;
    float* snc = smem3 + SNC_OFF;
    float* ss  = smem3 + SS_OFF;
    int*   sidx = (int*)(smem3 + SIDX_OFF);
    float* snum = smem3 + SNUM_OFF;
    float* sb  = smem3 + SB_OFF;

    int tid = threadIdx.x;
    int bid = blockIdx.x;                 // 0..295
    int b   = (bid >= BLKS_PER_B) ? 1 : 0;
    int lb  = bid - b * BLKS_PER_B;       // 0..147
    int nunits = (UNITS_PER_B - lb + BLKS_PER_B - 1) / BLKS_PER_B;   // 6 or 7
    const float* cbase = cond + (size_t)b * CIN * NSP;

    uint32_t sx_sb = (uint32_t)__cvta_generic_to_shared(sx);

    // prefetch unit 0 into buffer 0 (overlaps with preloads below)
    {
        const float* srcb = cbase + lb * 64;
#pragma unroll
        for (int r = 0; r < 4; r++) {
            int idx = tid + r * 256;       // float4 index 0..1023
            int k = idx >> 4, qd = idx & 15;
            cp_async16(sx_sb + (uint32_t)idx * 16, srcb + (size_t)k * NSP + qd * 4);
        }
        asm volatile("cp.async.commit_group;");
    }

    // preload weights, bias, centers; zero num partials
#pragma unroll
    for (int r = 0; r < 32; r++) sw[tid + r * 256] = cw[tid + r * 256];
    if (tid < 128) sb[tid] = cbias[tid];
#pragma unroll
    for (int r = 0; r < 4; r++) snc[tid + r * 256] = (&g_nc[0][0][0])[b * 1024 + tid + r * 256];
#pragma unroll
    for (int r = 0; r < 8; r++) snum[tid + r * 256] = 0.f;

    float alpha = *alpha_p, beta = *beta_p;

    int te = tid >> 4, tv = tid & 15;        // GEMM roles: 8 ec x 4 v per thread
    int ev_v = tid & 63, ev_e = tid >> 6;    // epilogue roles: (v, head)
    int half = tid >> 7, cix = tid & 127;    // accum roles
    int a_e = cix >> 5, a_c = cix & 31;
    int d_e = tid >> 6, d_m = (tid >> 3) & 7, d_g = tid & 7;   // den roles
    float den_acc = 0.f;

    __syncthreads();

    for (int ku = 0; ku < nunits; ku++) {
        int u = lb + ku * BLKS_PER_B;
        // prefetch next unit into other buffer
        if (ku + 1 < nunits) {
            const float* srcb = cbase + (size_t)(u + BLKS_PER_B) * 64;
            uint32_t dstb = sx_sb + (uint32_t)(((ku + 1) & 1) * 4096) * 4;
#pragma unroll
            for (int r = 0; r < 4; r++) {
                int idx = tid + r * 256;
                int k = idx >> 4, qd = idx & 15;
                cp_async16(dstb + (uint32_t)idx * 16, srcb + (size_t)k * NSP + qd * 4);
            }
            asm volatile("cp.async.commit_group;");
            asm volatile("cp.async.wait_group 1;");
        } else {
            asm volatile("cp.async.wait_group 0;");
        }
        __syncthreads();

        const float* sxc = sx + (ku & 1) * 4096;
        int v0 = u * 64;

        // --- register-blocked GEMM: feat[128][64] = W[128][64] * X[64][64] ---
        float acc[8][4];
#pragma unroll
        for (int j = 0; j < 8; j++)
#pragma unroll
            for (int jj = 0; jj < 4; jj++) acc[j][jj] = 0.f;

#pragma unroll 2
        for (int k0 = 0; k0 < 64; k0 += 4) {
            float4 x0 = *(const float4*)&sxc[(k0 + 0) * 64 + tv * 4];
            float4 x1 = *(const float4*)&sxc[(k0 + 1) * 64 + tv * 4];
            float4 x2 = *(const float4*)&sxc[(k0 + 2) * 64 + tv * 4];
            float4 x3 = *(const float4*)&sxc[(k0 + 3) * 64 + tv * 4];
#pragma unroll
            for (int j = 0; j < 8; j++) {
                float4 wr = *(const float4*)&sw[(te * 8 + j) * 64 + k0];
                acc[j][0] = fmaf(wr.w, x3.x, fmaf(wr.z, x2.x, fmaf(wr.y, x1.x, fmaf(wr.x, x0.x, acc[j][0]))));
                acc[j][1] = fmaf(wr.w, x3.y, fmaf(wr.z, x2.y, fmaf(wr.y, x1.y, fmaf(wr.x, x0.y, acc[j][1]))));
                acc[j][2] = fmaf(wr.w, x3.z, fmaf(wr.z, x2.z, fmaf(wr.y, x1.z, fmaf(wr.x, x0.z, acc[j][2]))));
                acc[j][3] = fmaf(wr.w, x3.w, fmaf(wr.z, x2.w, fmaf(wr.y, x1.w, fmaf(wr.x, x0.w, acc[j][3]))));
            }
        }
#pragma unroll
        for (int j = 0; j < 8; j++) {
            int ec = te * 8 + j;
            float bias = sb[ec];
            float4 f4;
            f4.x = __fadd_rn(acc[j][0], bias); f4.y = __fadd_rn(acc[j][1], bias);
            f4.z = __fadd_rn(acc[j][2], bias); f4.w = __fadd_rn(acc[j][3], bias);
            *(float4*)&sf[ec * SF_STR + tv * 4] = f4;
        }
        __syncthreads();

        // --- per (voxel, head): ref-style fp32 norm + sim + argmax ---
        // Streaming-c epilogue: Markstein quotient (bit-exact == __fdiv_rn)
        {
            int v = ev_v, e = ev_e;
            const float* fbase = &sf[(e * 32) * SF_STR + v];
            float ssq = 0.f;
#pragma unroll
            for (int c = 0; c < 32; c++) {
                float fc = fbase[c * SF_STR];
                ssq = __fadd_rn(ssq, __fmul_rn(fc, fc));
            }
            float nrm = fmaxf(__fsqrt_rn(ssq), 1e-12f);
            float rn_ = __frcp_rn(nrm);     // correctly-rounded reciprocal (Markstein seed)

            float dot[8];
#pragma unroll
            for (int m = 0; m < 8; m++) dot[m] = 0.f;
            const float* sncb = &snc[e * 8 * 32];
#pragma unroll
            for (int c = 0; c < 32; c++) {
                float fc = fbase[c * SF_STR];
                float q0 = __fmul_rn(fc, rn_);
                float e2 = __fmaf_rn(-nrm, q0, fc);
                float fn = __fmaf_rn(e2, rn_, q0);   // == __fdiv_rn(fc, nrm), bit-exact
#pragma unroll
                for (int m = 0; m < 8; m++)
                    dot[m] = fmaf(sncb[m * 32 + c], fn, dot[m]);
            }

            float t[8];
#pragma unroll
            for (int m = 0; m < 8; m++)
                t[m] = __fadd_rn(beta, __fmul_rn(alpha, dot[m]));

            float best = t[0], second = -3.4e38f; int bm = 0;
#pragma unroll
            for (int m = 1; m < 8; m++) {
                if (t[m] > best) { second = best; best = t[m]; bm = m; }
                else if (t[m] > second) second = t[m];
            }
            float sv;
            if (best - second > 4e-6f) {
                sv = sigmoid_ref(best);
            } else {
                float bs = -1.f; bm = 0;
#pragma unroll
                for (int m = 0; m < 8; m++) {
                    float sm = sigmoid_ref(t[m]);
                    if (sm > bs) { bs = sm; bm = m; }
                }
                sv = bs;
            }
            ss[e * 64 + v] = sv;
            sidx[e * 64 + v] = bm;
            int vlin = v0 + v;
            int h = vlin / 1600;
            int r = vlin - h * 1600;
            int w = r / 40;
            int d = r - w * 40;
            int nout = w * 1600 + h * 40 + d;
            g_s[b * 4 + e][nout] = sv;
            g_idx[b * 4 + e][nout] = (unsigned char)bm;
        }
        __syncthreads();

        // --- num accumulation: direct-indexed smem RMW, exclusive conflict-free slots ---
        {
            const float* frow = &sf[(a_e * 32 + a_c) * SF_STR + half * 32];
            const float* srow = &ss[a_e * 64 + half * 32];
            const int*   mrow = &sidx[a_e * 64 + half * 32];
            float* nbase = &snum[((half * 4 + a_e) * 8) * 32 + a_c];
#pragma unroll 8
            for (int vv = 0; vv < 32; vv++) {
                int ve = (vv + a_c) & 31;     // skew: conflict-free f reads
                float p = srow[ve] * frow[ve];
                int am = mrow[ve];
                nbase[am * 32] += p;
            }
        }
        // --- den partials: all 256 threads, (e, m, voxel-group-of-8) roles ---
        {
            const float* sden = &ss[d_e * 64 + d_g * 8];
            const int*   midx = &sidx[d_e * 64 + d_g * 8];
            float da = 0.f;
#pragma unroll
            for (int i = 0; i < 8; i++)
                da += (midx[i] == d_m) ? sden[i] : 0.f;
            den_acc += da;
        }
        __syncthreads();
    }

    // deterministic partials (no atomics), transposed layout for coalesced reduce
#pragma unroll
    for (int r = 0; r < 4; r++) {
        int i = tid + r * 256;
        g_partialT[b][i][lb] = snum[i] + snum[1024 + i];
    }
    g_partialT[b][1024 + tid][lb] = den_acc;
}

// ---------------- Kred: warp-per-element coalesced deterministic reduction ----------------
// 2560 elements, one warp each -> 320 blocks of 256
__global__ void k_red()
{
    int el   = blockIdx.x * 8 + (threadIdx.x >> 5);   // 0..2559
    int lane = threadIdx.x & 31;
    int b  = el / PARTW;
    int i  = el - b * PARTW;
    float sum = 0.f;
#pragma unroll
    for (int blk = lane; blk < BLKS_PER_B; blk += 32)
        sum += g_partialT[b][i][blk];
    sum += __shfl_xor_sync(0xffffffffu, sum, 16);
    sum += __shfl_xor_sync(0xffffffffu, sum, 8);
    sum += __shfl_xor_sync(0xffffffffu, sum, 4);
    sum += __shfl_xor_sync(0xffffffffu, sum, 2);
    sum += __shfl_xor_sync(0xffffffffu, sum, 1);
    if (lane == 0) {
        if (i < 1024) {
            (&g_num[0][0][0])[b * 1024 + i] = sum;
        } else {
            g_den8[b][i - 1024] = sum;     // [e*64 + m*8 + g]
        }
    }
}

// ---------------- K4: fold w into projection -> P ----------------
__global__ void k4_P(const float* __restrict__ pw)
{
    int b9 = blockIdx.x >> 3;
    int m  = blockIdx.x & 7;
    int b  = b9 >> 2, e = b9 & 3;
    __shared__ float wsh[32];
    int tid = threadIdx.x;   // 0..255 = o
    if (tid < 32) {
        float den = 0.f;
#pragma unroll
        for (int g = 0; g < 8; g++) den += g_den8[b][e * 64 + m * 8 + g];
        wsh[tid] = __fdiv_rn(__fadd_rn(g_num[b9][m][tid], g_cc[b9][m][tid]),
                             __fadd_rn(den, 1.0f));
    }
    __syncthreads();
    float p = 0.f;
#pragma unroll 8
    for (int c = 0; c < 32; c++) p = fmaf(pw[tid * ECH + e * CH + c], wsh[c], p);
    g_P[b][e][m][tid] = p;
}

// ---------------- K5: output = proj_b + sum_e s_e * P[b][e][idx_e][:] ----------------
// PPAD = 260: mod 32 == 4 -> row em's 16B segment = banks (4*id+o)%32, distinct
// per id (broadcast on equal id) => conflict-free LDS.128 P gathers.
#define PPAD 260
__global__ void __launch_bounds__(128) k5_out(const float* __restrict__ pb, float* __restrict__ out)
{
    __shared__ float Ps[32 * PPAD];
    __shared__ float pbs[256];
    int tid = threadIdx.x;
    int bx  = blockIdx.x;
    int b   = bx / 125;
    int chunk = bx - b * 125;

    const float* Pg = &g_P[b][0][0][0];
#pragma unroll
    for (int r = 0; r < 64; r++) {
        int idx = tid + r * 128;            // 0..8191
        int em = idx >> 8, o = idx & 255;
        Ps[em * PPAD + o] = Pg[idx];
    }
#pragma unroll
    for (int r = 0; r < 2; r++) pbs[tid + r * 128] = pb[tid + r * 128];

    int n0 = chunk * 512 + tid * 4;
    float4 sv[4];
    int off[4][4];
#pragma unroll
    for (int e = 0; e < 4; e++) {
        sv[e] = *(const float4*)&g_s[b * 4 + e][n0];
        uchar4 id = *(const uchar4*)&g_idx[b * 4 + e][n0];
        off[e][0] = (e * 8 + id.x) * PPAD;
        off[e][1] = (e * 8 + id.y) * PPAD;
        off[e][2] = (e * 8 + id.z) * PPAD;
        off[e][3] = (e * 8 + id.w) * PPAD;
    }
    __syncthreads();

    float* ob = out + (size_t)b * OUTC * NSP + n0;
    // 4-o blocks: float4 P loads (conflict-free), FMA order per output element
    // unchanged (pb + s0*P + s1*P + s2*P + s3*P, ascending e) -> bit-identical.
#pragma unroll 2
    for (int o = 0; o < 256; o += 4) {
        float4 pbq = *(const float4*)&pbs[o];
        // av[j] = output float4 across o..o+3 for voxel j
        float4 av0 = pbq, av1 = pbq, av2 = pbq, av3 = pbq;
#pragma unroll
        for (int e = 0; e < 4; e++) {
            float4 p0 = *(const float4*)&Ps[off[e][0] + o];
            float4 p1 = *(const float4*)&Ps[off[e][1] + o];
            float4 p2 = *(const float4*)&Ps[off[e][2] + o];
            float4 p3 = *(const float4*)&Ps[off[e][3] + o];
            av0.x = fmaf(sv[e].x, p0.x, av0.x); av0.y = fmaf(sv[e].x, p0.y, av0.y);
            av0.z = fmaf(sv[e].x, p0.z, av0.z); av0.w = fmaf(sv[e].x, p0.w, av0.w);
            av1.x = fmaf(sv[e].y, p1.x, av1.x); av1.y = fmaf(sv[e].y, p1.y, av1.y);
            av1.z = fmaf(sv[e].y, p1.z, av1.z); av1.w = fmaf(sv[e].y, p1.w, av1.w);
            av2.x = fmaf(sv[e].z, p2.x, av2.x); av2.y = fmaf(sv[e].z, p2.y, av2.y);
            av2.z = fmaf(sv[e].z, p2.z, av2.z); av2.w = fmaf(sv[e].z, p2.w, av2.w);
            av3.x = fmaf(sv[e].w, p3.x, av3.x); av3.y = fmaf(sv[e].w, p3.y, av3.y);
            av3.z = fmaf(sv[e].w, p3.z, av3.z); av3.w = fmaf(sv[e].w, p3.w, av3.w);
        }
        // store: for each o+k, float4 across the 4 voxels
        float4 s0 = make_float4(av0.x, av1.x, av2.x, av3.x);
        float4 s1 = make_float4(av0.y, av1.y, av2.y, av3.y);
        float4 s2 = make_float4(av0.z, av1.z, av2.z, av3.z);
        float4 s3 = make_float4(av0.w, av1.w, av2.w, av3.w);
        *(float4*)&ob[(size_t)(o + 0) * NSP] = s0;
        *(float4*)&ob[(size_t)(o + 1) * NSP] = s1;
        *(float4*)&ob[(size_t)(o + 2) * NSP] = s2;
        *(float4*)&ob[(size_t)(o + 3) * NSP] = s3;
    }
}

// ---------------- launch ----------------
extern "C" void kernel_launch(void* const* d_in, const int* in_sizes, int n_in,
                              void* d_out, int out_size)
{
    const float* x     = (const float*)d_in[0];
    const float* cond  = (const float*)d_in[1];
    const float* xw    = (const float*)d_in[2];
    const float* xb    = (const float*)d_in[3];
    const float* cw    = (const float*)d_in[4];
    const float* cb    = (const float*)d_in[5];
    const float* alpha = (const float*)d_in[6];
    const float* beta  = (const float*)d_in[7];
    const float* pw    = (const float*)d_in[8];
    const float* pb    = (const float*)d_in[9];
    float* out = (float*)d_out;
    (void)in_sizes; (void)n_in; (void)out_size;

    cudaFuncSetAttribute(k3_main, cudaFuncAttributeMaxDynamicSharedMemorySize, SMEM_BYTES);

    k1_blockmeans<<<256, 256>>>(x, cond);
    k2_centers<<<64, 32>>>(xw, xb, cw, cb);
    k3_main<<<2 * BLKS_PER_B, 256, SMEM_BYTES>>>(cond, cw, cb, alpha, beta);
    k_red<<<320, 256>>>();
    k4_P<<<64, 256>>>(pw);
    k5_out<<<2 * 125, 128>>>(pb, out);
}